// round 2
// baseline (speedup 1.0000x reference)
#include <cuda_runtime.h>
#include <cstdint>
#include <math.h>

#define NEXP 16
#define TOPK 4
#define HDIM 2048
#define IDIM 2048
#define TWO_I 4096
#define TMAX 4096
#define ALPHA 1.702f
#define LIMIT 7.0f

#define BM 128
#define BN 128
#define BK 16
#define PADA 20    // 20 floats = 80B, multiple of 16B, conflict-free A frag loads
#define PADB 136   // 136 floats = 544B, multiple of 16B, conflict-free B frag loads

// routing scratch (device globals: allocation-free kernel_launch)
__device__ int   g_cnt[NEXP];
__device__ int   g_tok[NEXP * TMAX];
__device__ float g_wt[NEXP * TMAX];
__device__ float g_act[134217728];   // NEXP * TMAX * IDIM fp32 activations

// ---------------- helpers ----------------

__device__ __forceinline__ uint32_t f2tf32(float x) {
  uint32_t r;
  asm("cvt.rna.tf32.f32 %0, %1;" : "=r"(r) : "f"(x));
  return r;
}

__device__ __forceinline__ void cp16(float* dst, const float* src, bool pred) {
  uint32_t d = (uint32_t)__cvta_generic_to_shared(dst);
  int sz = pred ? 16 : 0;
  asm volatile("cp.async.cg.shared.global [%0], [%1], 16, %2;" :: "r"(d), "l"(src), "r"(sz));
}

__device__ __forceinline__ void cp_commit() { asm volatile("cp.async.commit_group;"); }

__device__ __forceinline__ void mma_tf32(float* c, const uint32_t* a, const uint32_t* b) {
  asm volatile(
      "mma.sync.aligned.m16n8k8.row.col.f32.tf32.tf32.f32 "
      "{%0,%1,%2,%3}, {%4,%5,%6,%7}, {%8,%9}, {%0,%1,%2,%3};"
      : "+f"(c[0]), "+f"(c[1]), "+f"(c[2]), "+f"(c[3])
      : "r"(a[0]), "r"(a[1]), "r"(a[2]), "r"(a[3]), "r"(b[0]), "r"(b[1]));
}

// ---------------- router ----------------

__global__ void zero_cnt_kernel() {
  if (threadIdx.x < NEXP) g_cnt[threadIdx.x] = 0;
}

__global__ __launch_bounds__(256) void router_kernel(const float* __restrict__ x,
                                                     const float* __restrict__ rw,
                                                     const float* __restrict__ rb) {
  int warp = threadIdx.x >> 5, lane = threadIdx.x & 31;
  int t = blockIdx.x * 8 + warp;
  float acc[NEXP];
#pragma unroll
  for (int e = 0; e < NEXP; e++) acc[e] = 0.f;
  const float* xr = x + (size_t)t * HDIM;
  for (int h = lane; h < HDIM; h += 32) {
    float xv = xr[h];
#pragma unroll
    for (int e = 0; e < NEXP; e++) acc[e] = fmaf(xv, rw[e * HDIM + h], acc[e]);
  }
#pragma unroll
  for (int e = 0; e < NEXP; e++) {
#pragma unroll
    for (int o = 16; o > 0; o >>= 1) acc[e] += __shfl_xor_sync(0xffffffffu, acc[e], o);
  }
  if (lane == 0) {
    float v[NEXP];
#pragma unroll
    for (int e = 0; e < NEXP; e++) v[e] = acc[e] + rb[e];
    int ids[TOPK]; float vals[TOPK];
#pragma unroll
    for (int j = 0; j < TOPK; j++) {
      float best = -1e30f; int bi = 0;
#pragma unroll
      for (int e = 0; e < NEXP; e++)
        if (v[e] > best) { best = v[e]; bi = e; }
      ids[j] = bi; vals[j] = best; v[bi] = -1e30f;
    }
    float m = vals[0], s = 0.f, w[TOPK];
#pragma unroll
    for (int j = 0; j < TOPK; j++) { w[j] = expf(vals[j] - m); s += w[j]; }
    float inv = 1.f / s;
#pragma unroll
    for (int j = 0; j < TOPK; j++) {
      int e = ids[j];
      int p = atomicAdd(&g_cnt[e], 1);
      g_tok[e * TMAX + p] = t;
      g_wt[e * TMAX + p]  = w[j] * inv;
    }
  }
}

// ---------------- GEMM1: X @ w1[e] + b1 -> clipped GLU -> g_act ----------------

__device__ __forceinline__ void g1_load(const float* __restrict__ X, const float* __restrict__ w1e,
                                        float* As, float* Bg, float* Bu,
                                        int tid, int s, int kb, int n0, int tok0, int tok1) {
  int row = tid >> 2, c4 = (tid & 3) << 2;
  const float* srcA = X + (size_t)(tok0 < 0 ? 0 : tok0) * HDIM + kb * BK + c4;
  cp16(&As[(s * BM + row) * PADA + c4], srcA, tok0 >= 0);
  srcA = X + (size_t)(tok1 < 0 ? 0 : tok1) * HDIM + kb * BK + c4;
  cp16(&As[(s * BM + row + 64) * PADA + c4], srcA, tok1 >= 0);
#pragma unroll
  for (int i = 0; i < 2; i++) {
    int idx = tid + i * 256;
    int brow = idx >> 5, c = (idx & 31) << 2;
    const float* srcg = w1e + (size_t)(kb * BK + brow) * TWO_I + n0 + c;
    cp16(&Bg[(s * BK + brow) * PADB + c], srcg, true);
    cp16(&Bu[(s * BK + brow) * PADB + c], srcg + IDIM, true);
  }
}

__global__ __launch_bounds__(256, 1) void gemm1_kernel(const float* __restrict__ X,
                                                       const float* __restrict__ w1,
                                                       const float* __restrict__ b1) {
  int e = blockIdx.z;
  int cnt = g_cnt[e];
  int m0 = blockIdx.y * BM;
  if (m0 >= cnt) return;
  int n0 = blockIdx.x * BN;

  extern __shared__ float smem[];
  float* As = smem;                       // 2*128*20
  float* Bg = As + 2 * BM * PADA;         // 2*16*136
  float* Bu = Bg + 2 * BK * PADB;         // 2*16*136
  int* toks = (int*)(Bu + 2 * BK * PADB); // 128

  int tid = threadIdx.x;
  if (tid < BM) {
    int r = m0 + tid;
    toks[tid] = (r < cnt) ? g_tok[e * TMAX + r] : -1;
  }
  __syncthreads();

  int arow = tid >> 2;
  int tok0 = toks[arow], tok1 = toks[arow + 64];

  const float* w1e = w1 + (size_t)e * HDIM * TWO_I;

  int warp = tid >> 5, lane = tid & 31;
  int wm = (warp >> 1) * 32, wn = (warp & 1) * 64;
  int g = lane >> 2, tq = lane & 3;

  float cg[2][8][4], cu[2][8][4];
#pragma unroll
  for (int mi = 0; mi < 2; mi++)
#pragma unroll
    for (int ni = 0; ni < 8; ni++)
#pragma unroll
      for (int q = 0; q < 4; q++) { cg[mi][ni][q] = 0.f; cu[mi][ni][q] = 0.f; }

  g1_load(X, w1e, As, Bg, Bu, tid, 0, 0, n0, tok0, tok1);
  cp_commit();

  const int NK = HDIM / BK;
  for (int kb = 0; kb < NK; kb++) {
    int s = kb & 1;
    if (kb + 1 < NK) {
      g1_load(X, w1e, As, Bg, Bu, tid, s ^ 1, kb + 1, n0, tok0, tok1);
      cp_commit();
      asm volatile("cp.async.wait_group 1;");
    } else {
      asm volatile("cp.async.wait_group 0;");
    }
    __syncthreads();
#pragma unroll
    for (int kk = 0; kk < 2; kk++) {
      uint32_t af[2][4];
#pragma unroll
      for (int mi = 0; mi < 2; mi++) {
        const float* ab = &As[(s * BM + wm + mi * 16) * PADA + kk * 8];
        af[mi][0] = f2tf32(ab[g * PADA + tq]);
        af[mi][1] = f2tf32(ab[(g + 8) * PADA + tq]);
        af[mi][2] = f2tf32(ab[g * PADA + tq + 4]);
        af[mi][3] = f2tf32(ab[(g + 8) * PADA + tq + 4]);
      }
#pragma unroll
      for (int ni = 0; ni < 8; ni++) {
        int col = wn + ni * 8 + g;
        const float* bgp = &Bg[(s * BK + kk * 8 + tq) * PADB + col];
        const float* bup = &Bu[(s * BK + kk * 8 + tq) * PADB + col];
        uint32_t bfg[2], bfu[2];
        bfg[0] = f2tf32(bgp[0]);
        bfg[1] = f2tf32(bgp[4 * PADB]);
        bfu[0] = f2tf32(bup[0]);
        bfu[1] = f2tf32(bup[4 * PADB]);
#pragma unroll
        for (int mi = 0; mi < 2; mi++) {
          mma_tf32(cg[mi][ni], af[mi], bfg);
          mma_tf32(cu[mi][ni], af[mi], bfu);
        }
      }
    }
    __syncthreads();
  }

  const float* b1e = b1 + (size_t)e * TWO_I;
#pragma unroll
  for (int mi = 0; mi < 2; mi++) {
#pragma unroll
    for (int rr = 0; rr < 2; rr++) {
      int r = m0 + wm + mi * 16 + rr * 8 + g;
      if (r >= cnt) continue;
      float* ar = g_act + ((size_t)e * TMAX + r) * IDIM;
#pragma unroll
      for (int ni = 0; ni < 8; ni++) {
        int c = n0 + wn + ni * 8 + (tq << 1);
#pragma unroll
        for (int q = 0; q < 2; q++) {
          float gv = cg[mi][ni][rr * 2 + q] + b1e[c + q];
          float uv = cu[mi][ni][rr * 2 + q] + b1e[IDIM + c + q];
          gv = fminf(gv, LIMIT);
          uv = fminf(fmaxf(uv, -LIMIT), LIMIT);
          float sig = 1.f / (1.f + expf(-ALPHA * gv));
          ar[c + q] = (uv + 1.f) * gv * sig;
        }
      }
    }
  }
}

// ---------------- GEMM2: act @ w2[e] + b2 -> weighted scatter-add ----------------

__device__ __forceinline__ void g2_load(const float* __restrict__ w2e,
                                        float* As, float* Bs,
                                        int tid, int s, int kb, int n0, int e, int m0, int cnt) {
  int row = tid >> 2, c4 = (tid & 3) << 2;
  const float* srcA = g_act + ((size_t)e * TMAX + m0 + row) * IDIM + kb * BK + c4;
  cp16(&As[(s * BM + row) * PADA + c4], srcA, (m0 + row) < cnt);
  srcA = g_act + ((size_t)e * TMAX + m0 + row + 64) * IDIM + kb * BK + c4;
  cp16(&As[(s * BM + row + 64) * PADA + c4], srcA, (m0 + row + 64) < cnt);
#pragma unroll
  for (int i = 0; i < 2; i++) {
    int idx = tid + i * 256;
    int brow = idx >> 5, c = (idx & 31) << 2;
    const float* srcB = w2e + (size_t)(kb * BK + brow) * HDIM + n0 + c;
    cp16(&Bs[(s * BK + brow) * PADB + c], srcB, true);
  }
}

__global__ __launch_bounds__(256, 1) void gemm2_kernel(const float* __restrict__ w2,
                                                       const float* __restrict__ b2,
                                                       float* __restrict__ out) {
  int e = blockIdx.z;
  int cnt = g_cnt[e];
  int m0 = blockIdx.y * BM;
  if (m0 >= cnt) return;
  int n0 = blockIdx.x * BN;

  extern __shared__ float smem[];
  float* As = smem;                        // 2*128*20
  float* Bs = As + 2 * BM * PADA;          // 2*16*136
  int* toks = (int*)(Bs + 2 * BK * PADB);  // 128
  float* wts = (float*)(toks + BM);        // 128

  int tid = threadIdx.x;
  if (tid < BM) {
    int r = m0 + tid;
    bool v = r < cnt;
    toks[tid] = v ? g_tok[e * TMAX + r] : 0;
    wts[tid]  = v ? g_wt[e * TMAX + r] : 0.f;
  }
  __syncthreads();

  const float* w2e = w2 + (size_t)e * IDIM * HDIM;

  int warp = tid >> 5, lane = tid & 31;
  int wm = (warp >> 1) * 32, wn = (warp & 1) * 64;
  int g = lane >> 2, tq = lane & 3;

  float cc[2][8][4];
#pragma unroll
  for (int mi = 0; mi < 2; mi++)
#pragma unroll
    for (int ni = 0; ni < 8; ni++)
#pragma unroll
      for (int q = 0; q < 4; q++) cc[mi][ni][q] = 0.f;

  g2_load(w2e, As, Bs, tid, 0, 0, n0, e, m0, cnt);
  cp_commit();

  const int NK = IDIM / BK;
  for (int kb = 0; kb < NK; kb++) {
    int s = kb & 1;
    if (kb + 1 < NK) {
      g2_load(w2e, As, Bs, tid, s ^ 1, kb + 1, n0, e, m0, cnt);
      cp_commit();
      asm volatile("cp.async.wait_group 1;");
    } else {
      asm volatile("cp.async.wait_group 0;");
    }
    __syncthreads();
#pragma unroll
    for (int kk = 0; kk < 2; kk++) {
      uint32_t af[2][4];
#pragma unroll
      for (int mi = 0; mi < 2; mi++) {
        const float* ab = &As[(s * BM + wm + mi * 16) * PADA + kk * 8];
        af[mi][0] = f2tf32(ab[g * PADA + tq]);
        af[mi][1] = f2tf32(ab[(g + 8) * PADA + tq]);
        af[mi][2] = f2tf32(ab[g * PADA + tq + 4]);
        af[mi][3] = f2tf32(ab[(g + 8) * PADA + tq + 4]);
      }
#pragma unroll
      for (int ni = 0; ni < 8; ni++) {
        int col = wn + ni * 8 + g;
        const float* bp = &Bs[(s * BK + kk * 8 + tq) * PADB + col];
        uint32_t bf[2];
        bf[0] = f2tf32(bp[0]);
        bf[1] = f2tf32(bp[4 * PADB]);
#pragma unroll
        for (int mi = 0; mi < 2; mi++) mma_tf32(cc[mi][ni], af[mi], bf);
      }
    }
    __syncthreads();
  }

  const float* b2e = b2 + (size_t)e * HDIM;
#pragma unroll
  for (int mi = 0; mi < 2; mi++) {
#pragma unroll
    for (int rr = 0; rr < 2; rr++) {
      int lr = wm + mi * 16 + rr * 8 + g;
      int r = m0 + lr;
      if (r >= cnt) continue;
      int t = toks[lr];
      float w = wts[lr];
      float* orow = out + (size_t)t * HDIM;
#pragma unroll
      for (int ni = 0; ni < 8; ni++) {
        int c = n0 + wn + ni * 8 + (tq << 1);
        atomicAdd(&orow[c],     w * (cc[mi][ni][rr * 2 + 0] + b2e[c]));
        atomicAdd(&orow[c + 1], w * (cc[mi][ni][rr * 2 + 1] + b2e[c + 1]));
      }
    }
  }
}

// ---------------- launch ----------------

#define SMEM1_BYTES ((2 * BM * PADA + 4 * BK * PADB) * 4 + BM * 4)
#define SMEM2_BYTES ((2 * BM * PADA + 2 * BK * PADB) * 4 + BM * 8)

extern "C" void kernel_launch(void* const* d_in, const int* in_sizes, int n_in,
                              void* d_out, int out_size) {
  (void)in_sizes; (void)n_in; (void)out_size;
  const float* hs = (const float*)d_in[0];
  const float* rw = (const float*)d_in[1];
  const float* rb = (const float*)d_in[2];
  const float* w1 = (const float*)d_in[3];
  const float* b1 = (const float*)d_in[4];
  const float* w2 = (const float*)d_in[5];
  const float* b2 = (const float*)d_in[6];
  float* out = (float*)d_out;

  cudaMemsetAsync(out, 0, (size_t)TMAX * HDIM * sizeof(float));
  zero_cnt_kernel<<<1, 32>>>();
  router_kernel<<<TMAX / 8, 256>>>(hs, rw, rb);

  cudaFuncSetAttribute(gemm1_kernel, cudaFuncAttributeMaxDynamicSharedMemorySize, SMEM1_BYTES);
  cudaFuncSetAttribute(gemm2_kernel, cudaFuncAttributeMaxDynamicSharedMemorySize, SMEM2_BYTES);

  dim3 grid1(IDIM / BN, TMAX / BM, NEXP);
  gemm1_kernel<<<grid1, 256, SMEM1_BYTES>>>(hs, w1, b1);
  dim3 grid2(HDIM / BN, TMAX / BM, NEXP);
  gemm2_kernel<<<grid2, 256, SMEM2_BYTES>>>(w2, b2, out);
}

// round 4
// speedup vs baseline: 1.7048x; 1.7048x over previous
#include <cuda_runtime.h>
#include <cuda_fp16.h>
#include <cstdint>
#include <math.h>

#define NEXP 16
#define TOPK 4
#define HDIM 2048
#define IDIM 2048
#define TMAX 4096
#define ALPHA 1.702f
#define LIMIT 7.0f
#define NKB 32     // 2048 / 64
#define KH 64      // halfs of K per stage
#define LDKB 144   // bytes per padded row (72 halfs)

__device__ int    g_cnt[NEXP];
__device__ int    g_tok[NEXP * TMAX];
__device__ int    g_tslot[TMAX * TOPK];
__device__ float  g_twt[TMAX * TOPK];
__device__ __half g_xh[(size_t)TMAX * HDIM];
__device__ __half g_w1h[(size_t)NEXP * 2 * IDIM * HDIM];  // [e][n=4096][k=2048]
__device__ __half g_w2h[(size_t)NEXP * HDIM * IDIM];      // [e][n=2048][k=2048]
__device__ __half g_acth[(size_t)NEXP * TMAX * IDIM];     // [e][slot][i]
__device__ float  g_part[(size_t)NEXP * TMAX * HDIM];     // [e][slot][h]

// ---------------- helpers ----------------
__device__ __forceinline__ void cp16(const void* smem_dst, const void* gsrc, bool pred) {
  uint32_t d = (uint32_t)__cvta_generic_to_shared(smem_dst);
  int sz = pred ? 16 : 0;
  asm volatile("cp.async.cg.shared.global [%0], [%1], 16, %2;" :: "r"(d), "l"(gsrc), "r"(sz));
}
__device__ __forceinline__ void cp_commit() { asm volatile("cp.async.commit_group;"); }
__device__ __forceinline__ void cp_wait0() { asm volatile("cp.async.wait_group 0;"); }

__device__ __forceinline__ void mma16(float* c, const uint32_t* a, const uint32_t* b) {
  asm volatile(
      "mma.sync.aligned.m16n8k16.row.col.f32.f16.f16.f32 "
      "{%0,%1,%2,%3}, {%4,%5,%6,%7}, {%8,%9}, {%0,%1,%2,%3};"
      : "+f"(c[0]), "+f"(c[1]), "+f"(c[2]), "+f"(c[3])
      : "r"(a[0]), "r"(a[1]), "r"(a[2]), "r"(a[3]), "r"(b[0]), "r"(b[1]));
}
__device__ __forceinline__ uint32_t lds32(const char* smem, uint32_t off) {
  return *(const uint32_t*)(smem + off);
}

// ---------------- router ----------------
__global__ void zero_cnt_kernel() { if (threadIdx.x < NEXP) g_cnt[threadIdx.x] = 0; }

__global__ __launch_bounds__(256) void router_kernel(const float* __restrict__ x,
                                                     const float* __restrict__ rw,
                                                     const float* __restrict__ rb) {
  int warp = threadIdx.x >> 5, lane = threadIdx.x & 31;
  int t = blockIdx.x * 8 + warp;
  float acc[NEXP];
#pragma unroll
  for (int e = 0; e < NEXP; e++) acc[e] = 0.f;
  const float* xr = x + (size_t)t * HDIM;
  for (int h = lane; h < HDIM; h += 32) {
    float xv = xr[h];
#pragma unroll
    for (int e = 0; e < NEXP; e++) acc[e] = fmaf(xv, rw[e * HDIM + h], acc[e]);
  }
#pragma unroll
  for (int e = 0; e < NEXP; e++)
#pragma unroll
    for (int o = 16; o > 0; o >>= 1) acc[e] += __shfl_xor_sync(0xffffffffu, acc[e], o);
  if (lane == 0) {
    float v[NEXP];
#pragma unroll
    for (int e = 0; e < NEXP; e++) v[e] = acc[e] + rb[e];
    int ids[TOPK]; float vals[TOPK];
#pragma unroll
    for (int j = 0; j < TOPK; j++) {
      float best = -1e30f; int bi = 0;
#pragma unroll
      for (int e = 0; e < NEXP; e++)
        if (v[e] > best) { best = v[e]; bi = e; }
      ids[j] = bi; vals[j] = best; v[bi] = -1e30f;
    }
    float m = vals[0], s = 0.f, w[TOPK];
#pragma unroll
    for (int j = 0; j < TOPK; j++) { w[j] = expf(vals[j] - m); s += w[j]; }
    float inv = 1.f / s;
#pragma unroll
    for (int j = 0; j < TOPK; j++) {
      int e = ids[j];
      int p = atomicAdd(&g_cnt[e], 1);
      g_tok[e * TMAX + p] = t;
      g_tslot[t * TOPK + j] = e * TMAX + p;
      g_twt[t * TOPK + j] = w[j] * inv;
    }
  }
}

// ---------------- prep: fp16 convert X, transpose+convert weights ----------------
__global__ __launch_bounds__(256) void cvtx_kernel(const float* __restrict__ x) {
  size_t i = ((size_t)blockIdx.x * 256 + threadIdx.x);
  float4 v = ((const float4*)x)[i];
  __half2 h0 = __floats2half2_rn(v.x, v.y);
  __half2 h1 = __floats2half2_rn(v.z, v.w);
  uint2 o = { *(uint32_t*)&h0, *(uint32_t*)&h1 };
  ((uint2*)g_xh)[i] = o;
}

// src: [e][R(k)][C(n)] fp32  ->  dst: [e][C(n)][R(k)] fp16
__global__ __launch_bounds__(256) void transpose_h_kernel(const float* __restrict__ src,
                                                          __half* __restrict__ dst,
                                                          int R, int C) {
  __shared__ float tile[32][33];
  int e = blockIdx.z;
  const float* s = src + (size_t)e * R * C;
  __half* d = dst + (size_t)e * R * C;
  int r0 = blockIdx.y * 32, c0 = blockIdx.x * 32;
  int tr = threadIdx.x >> 3, tc = (threadIdx.x & 7) << 2;
  float4 v = *(const float4*)(s + (size_t)(r0 + tr) * C + c0 + tc);
  tile[tr][tc] = v.x; tile[tr][tc + 1] = v.y; tile[tr][tc + 2] = v.z; tile[tr][tc + 3] = v.w;
  __syncthreads();
  int on = tr, kc = tc;  // output row = n (c0+on), k chunk
  __half2 h0 = __floats2half2_rn(tile[kc][on],     tile[kc + 1][on]);
  __half2 h1 = __floats2half2_rn(tile[kc + 2][on], tile[kc + 3][on]);
  uint2 o = { *(uint32_t*)&h0, *(uint32_t*)&h1 };
  *(uint2*)(d + (size_t)(c0 + on) * R + r0 + kc) = o;
}

// ---------------- GEMM1: X @ w1 (gate|up) -> clipped GLU -> g_acth ----------------
// smem: stage s at s*55296: A [128 rows x 144B] at +0, B [256 rows x 144B] at +18432
// toks[128] ints at 110592.  total 111104 bytes.
#define SMEM1 111104
#define STG1 55296

__global__ __launch_bounds__(512, 1) void gemm1_kernel(const float* __restrict__ b1) {
  int e = blockIdx.z;
  int cnt = g_cnt[e];
  int m0 = blockIdx.x * 128;
  if (m0 >= cnt) return;
  int n0 = blockIdx.y * 128;

  extern __shared__ __align__(16) char smem[];
  int* toks = (int*)(smem + 110592);
  int tid = threadIdx.x, w = tid >> 5, lane = tid & 31;
  int g = lane >> 2, tq = lane & 3;

  if (tid < 128) toks[tid] = (m0 + tid < cnt) ? g_tok[e * TMAX + m0 + tid] : -1;
  __syncthreads();

  // cp.async setup: A rows tid>>3 and +64, chunk tid&7 (16B of k)
  int ar0 = tid >> 3, chunk = tid & 7;
  int t0 = toks[ar0], t1 = toks[ar0 + 64];
  const __half* a0src = g_xh + (size_t)(t0 < 0 ? 0 : t0) * HDIM + chunk * 8;
  const __half* a1src = g_xh + (size_t)(t1 < 0 ? 0 : t1) * HDIM + chunk * 8;
  bool p0 = t0 >= 0, p1 = t1 >= 0;
  uint32_t adst0 = ar0 * LDKB + chunk * 16;
  uint32_t adst1 = (ar0 + 64) * LDKB + chunk * 16;

  const __half* w1e = g_w1h + (size_t)e * 4096 * 2048;
  const __half* bsrc[4]; uint32_t bdst[4];
#pragma unroll
  for (int q = 0; q < 4; q++) {
    int row = ar0 + 64 * q;                           // 0..255
    int n = (row < 128) ? (n0 + row) : (2048 + n0 + row - 128);
    bsrc[q] = w1e + (size_t)n * 2048 + chunk * 8;
    bdst[q] = 18432 + row * LDKB + chunk * 16;
  }

  auto ld = [&](int kb, int s) {
    char* base = smem + s * STG1;
    int ko = kb * KH;
    cp16(base + adst0, a0src + ko, p0);
    cp16(base + adst1, a1src + ko, p1);
#pragma unroll
    for (int q = 0; q < 4; q++) cp16(base + bdst[q], bsrc[q] + ko, true);
    cp_commit();
  };

  float cg[2][4][4], cu[2][4][4];
#pragma unroll
  for (int mi = 0; mi < 2; mi++)
#pragma unroll
    for (int ni = 0; ni < 4; ni++)
#pragma unroll
      for (int q = 0; q < 4; q++) { cg[mi][ni][q] = 0.f; cu[mi][ni][q] = 0.f; }

  int wm = (w & 3) * 32, wn = (w >> 2) * 32;
  ld(0, 0);

  for (int kb = 0; kb < NKB; kb++) {
    cp_wait0();
    __syncthreads();
    if (kb + 1 < NKB) ld(kb + 1, (kb + 1) & 1);
    const char* Ab = smem + (kb & 1) * STG1;
    const char* Bb = Ab + 18432;
#pragma unroll
    for (int kk = 0; kk < 4; kk++) {
      uint32_t kobyte = kk * 32 + tq * 4;
      uint32_t a[2][4];
#pragma unroll
      for (int mi = 0; mi < 2; mi++) {
        uint32_t base = (wm + mi * 16 + g) * LDKB + kobyte;
        a[mi][0] = lds32(Ab, base);
        a[mi][1] = lds32(Ab, base + 8 * LDKB);
        a[mi][2] = lds32(Ab, base + 16);
        a[mi][3] = lds32(Ab, base + 8 * LDKB + 16);
      }
#pragma unroll
      for (int ni = 0; ni < 4; ni++) {
        uint32_t nb = (wn + ni * 8 + g) * LDKB + kobyte;
        uint32_t bg[2], bu[2];
        bg[0] = lds32(Bb, nb);
        bg[1] = lds32(Bb, nb + 16);
        bu[0] = lds32(Bb, nb + 128 * LDKB);
        bu[1] = lds32(Bb, nb + 128 * LDKB + 16);
#pragma unroll
        for (int mi = 0; mi < 2; mi++) {
          mma16(cg[mi][ni], a[mi], bg);
          mma16(cu[mi][ni], a[mi], bu);
        }
      }
    }
  }

  // epilogue: bias + clipped GLU -> fp16 acts
  const float* b1e = b1 + (size_t)e * 4096;
#pragma unroll
  for (int ni = 0; ni < 4; ni++) {
    int col = n0 + wn + ni * 8 + 2 * tq;
    float bg0 = b1e[col], bg1 = b1e[col + 1];
    float bu0 = b1e[2048 + col], bu1 = b1e[2048 + col + 1];
#pragma unroll
    for (int mi = 0; mi < 2; mi++) {
#pragma unroll
      for (int rr = 0; rr < 2; rr++) {
        int rl = wm + mi * 16 + rr * 8 + g;
        if (m0 + rl >= cnt) continue;
        float gv0 = cg[mi][ni][rr * 2 + 0] + bg0;
        float gv1 = cg[mi][ni][rr * 2 + 1] + bg1;
        float uv0 = cu[mi][ni][rr * 2 + 0] + bu0;
        float uv1 = cu[mi][ni][rr * 2 + 1] + bu1;
        gv0 = fminf(gv0, LIMIT); gv1 = fminf(gv1, LIMIT);
        uv0 = fminf(fmaxf(uv0, -LIMIT), LIMIT);
        uv1 = fminf(fmaxf(uv1, -LIMIT), LIMIT);
        float a0 = (uv0 + 1.f) * gv0 / (1.f + __expf(-ALPHA * gv0));
        float a1 = (uv1 + 1.f) * gv1 / (1.f + __expf(-ALPHA * gv1));
        __half2 h = __floats2half2_rn(a0, a1);
        *(__half2*)(g_acth + ((size_t)e * TMAX + m0 + rl) * 2048 + col) = h;
      }
    }
  }
}

// ---------------- GEMM2: acts @ w2 -> g_part ----------------
// smem: stage s at s*36864: A at +0 (128x144B), B at +18432 (128x144B). total 73728.
#define SMEM2 73728
#define STG2 36864

__global__ __launch_bounds__(256, 2) void gemm2_kernel() {
  int e = blockIdx.z;
  int cnt = g_cnt[e];
  int m0 = blockIdx.x * 128;
  if (m0 >= cnt) return;
  int n0 = blockIdx.y * 128;

  extern __shared__ __align__(16) char smem[];
  int tid = threadIdx.x, w = tid >> 5, lane = tid & 31;
  int g = lane >> 2, tq = lane & 3;

  const __half* acte = g_acth + (size_t)e * TMAX * 2048;
  const __half* w2e = g_w2h + (size_t)e * 2048 * 2048;

  const __half* asrc[4]; uint32_t adst[4]; bool apred[4];
  const __half* bsrc[4]; uint32_t bdst[4];
#pragma unroll
  for (int q = 0; q < 4; q++) {
    int idx = tid + q * 256;
    int row = idx >> 3, chunk = idx & 7;
    apred[q] = (m0 + row) < cnt;
    asrc[q] = acte + (size_t)(m0 + row) * 2048 + chunk * 8;
    adst[q] = row * LDKB + chunk * 16;
    bsrc[q] = w2e + (size_t)(n0 + row) * 2048 + chunk * 8;
    bdst[q] = 18432 + row * LDKB + chunk * 16;
  }

  auto ld = [&](int kb, int s) {
    char* base = smem + s * STG2;
    int ko = kb * KH;
#pragma unroll
    for (int q = 0; q < 4; q++) {
      cp16(base + adst[q], asrc[q] + ko, apred[q]);
      cp16(base + bdst[q], bsrc[q] + ko, true);
    }
    cp_commit();
  };

  float cc[2][8][4];
#pragma unroll
  for (int mi = 0; mi < 2; mi++)
#pragma unroll
    for (int ni = 0; ni < 8; ni++)
#pragma unroll
      for (int q = 0; q < 4; q++) cc[mi][ni][q] = 0.f;

  int wm = (w & 3) * 32, wn = (w >> 2) * 64;
  ld(0, 0);

  for (int kb = 0; kb < NKB; kb++) {
    cp_wait0();
    __syncthreads();
    if (kb + 1 < NKB) ld(kb + 1, (kb + 1) & 1);
    const char* Ab = smem + (kb & 1) * STG2;
    const char* Bb = Ab + 18432;
#pragma unroll
    for (int kk = 0; kk < 4; kk++) {
      uint32_t kobyte = kk * 32 + tq * 4;
      uint32_t a[2][4];
#pragma unroll
      for (int mi = 0; mi < 2; mi++) {
        uint32_t base = (wm + mi * 16 + g) * LDKB + kobyte;
        a[mi][0] = lds32(Ab, base);
        a[mi][1] = lds32(Ab, base + 8 * LDKB);
        a[mi][2] = lds32(Ab, base + 16);
        a[mi][3] = lds32(Ab, base + 8 * LDKB + 16);
      }
#pragma unroll
      for (int ni = 0; ni < 8; ni++) {
        uint32_t nb = (wn + ni * 8 + g) * LDKB + kobyte;
        uint32_t b[2];
        b[0] = lds32(Bb, nb);
        b[1] = lds32(Bb, nb + 16);
#pragma unroll
        for (int mi = 0; mi < 2; mi++) mma16(cc[mi][ni], a[mi], b);
      }
    }
  }

  float* parte = g_part + (size_t)e * TMAX * 2048;
#pragma unroll
  for (int mi = 0; mi < 2; mi++) {
#pragma unroll
    for (int rr = 0; rr < 2; rr++) {
      int rl = wm + mi * 16 + rr * 8 + g;
      if (m0 + rl >= cnt) continue;
      float* prow = parte + (size_t)(m0 + rl) * 2048 + n0;
#pragma unroll
      for (int ni = 0; ni < 8; ni++) {
        float2 v = { cc[mi][ni][rr * 2 + 0], cc[mi][ni][rr * 2 + 1] };
        *(float2*)(prow + wn + ni * 8 + 2 * tq) = v;
      }
    }
  }
}

// ---------------- gather: out[t] = sum_j w_j * (part[slot_j] + b2[e_j]) ----------------
__global__ __launch_bounds__(256) void gather_kernel(const float* __restrict__ b2,
                                                     float* __restrict__ out) {
  int t = blockIdx.y;
  int h = blockIdx.x * 1024 + threadIdx.x * 4;
  float4 acc = {0.f, 0.f, 0.f, 0.f};
#pragma unroll
  for (int j = 0; j < TOPK; j++) {
    int sidx = g_tslot[t * TOPK + j];
    float wj = g_twt[t * TOPK + j];
    int e = sidx >> 12;
    float4 p = *(const float4*)(g_part + (size_t)sidx * 2048 + h);
    float4 b = *(const float4*)(b2 + (size_t)e * 2048 + h);
    acc.x += wj * (p.x + b.x);
    acc.y += wj * (p.y + b.y);
    acc.z += wj * (p.z + b.z);
    acc.w += wj * (p.w + b.w);
  }
  *(float4*)(out + (size_t)t * 2048 + h) = acc;
}

// ---------------- launch ----------------
extern "C" void kernel_launch(void* const* d_in, const int* in_sizes, int n_in,
                              void* d_out, int out_size) {
  (void)in_sizes; (void)n_in; (void)out_size;
  const float* hs = (const float*)d_in[0];
  const float* rw = (const float*)d_in[1];
  const float* rb = (const float*)d_in[2];
  const float* w1 = (const float*)d_in[3];
  const float* b1 = (const float*)d_in[4];
  const float* w2 = (const float*)d_in[5];
  const float* b2 = (const float*)d_in[6];
  float* out = (float*)d_out;

  void *pw1, *pw2;
  cudaGetSymbolAddress(&pw1, g_w1h);
  cudaGetSymbolAddress(&pw2, g_w2h);

  zero_cnt_kernel<<<1, 32>>>();
  router_kernel<<<TMAX / 8, 256>>>(hs, rw, rb);
  cvtx_kernel<<<(TMAX * HDIM) / 1024, 256>>>(hs);
  {
    dim3 g(4096 / 32, 2048 / 32, NEXP);
    transpose_h_kernel<<<g, 256>>>(w1, (__half*)pw1, 2048, 4096);
  }
  {
    dim3 g(2048 / 32, 2048 / 32, NEXP);
    transpose_h_kernel<<<g, 256>>>(w2, (__half*)pw2, 2048, 2048);
  }

  cudaFuncSetAttribute(gemm1_kernel, cudaFuncAttributeMaxDynamicSharedMemorySize, SMEM1);
  cudaFuncSetAttribute(gemm2_kernel, cudaFuncAttributeMaxDynamicSharedMemorySize, SMEM2);

  dim3 g1(TMAX / 128, 16, NEXP);   // x = m-tiles (fastest), y = n-tiles, z = expert
  gemm1_kernel<<<g1, 512, SMEM1>>>(b1);
  dim3 g2(TMAX / 128, 16, NEXP);
  gemm2_kernel<<<g2, 256, SMEM2>>>();
  dim3 gg(2, TMAX);
  gather_kernel<<<gg, 256>>>(b2, out);
}